// round 15
// baseline (speedup 1.0000x reference)
#include <cuda_runtime.h>
#include <math.h>

#define Bn 4
#define Rn 512
#define Cn 512
#define En 256
#define Hn 16
#define Dn 16
#define Mn 16
#define Fn 512

// ---------------- packed f32x2 helpers ----------------
typedef unsigned long long u64;
typedef unsigned int u32;
struct __align__(16) U2 { u64 a, b; };

__device__ __forceinline__ u64 pk(float lo, float hi) {
    u64 r; asm("mov.b64 %0,{%1,%2};" : "=l"(r) : "f"(lo), "f"(hi)); return r;
}
__device__ __forceinline__ void upk(u64 v, float& lo, float& hi) {
    asm("mov.b64 {%0,%1},%2;" : "=f"(lo), "=f"(hi) : "l"(v));
}
__device__ __forceinline__ u64 fma2(u64 a, u64 b, u64 c) {
    u64 d; asm("fma.rn.f32x2 %0,%1,%2,%3;" : "=l"(d) : "l"(a), "l"(b), "l"(c)); return d;
}
__device__ __forceinline__ u64 add2(u64 a, u64 b) {
    u64 d; asm("add.rn.f32x2 %0,%1,%2;" : "=l"(d) : "l"(a), "l"(b)); return d;
}
__device__ __forceinline__ u64 abs2(u64 x) { return x & 0x7FFFFFFF7FFFFFFFULL; }
__device__ __forceinline__ u64 shflx2(u64 v, int m) {
    float lo, hi; upk(v, lo, hi);
    lo = __shfl_xor_sync(0xFFFFFFFFu, lo, m);
    hi = __shfl_xor_sync(0xFFFFFFFFu, hi, m);
    return pk(lo, hi);
}

// ---------------- tf32 helpers ----------------
__device__ __forceinline__ void split_tf32(float v, float& hi, float& lo) {
    u32 h, l;
    asm("cvt.rna.tf32.f32 %0, %1;" : "=r"(h) : "f"(v));
    hi = __uint_as_float(h);
    float r = v - hi;
    asm("cvt.rna.tf32.f32 %0, %1;" : "=r"(l) : "f"(r));
    lo = __uint_as_float(l);
}
__device__ __forceinline__ void mma8(float* d, u32 a0, u32 a1, u32 a2, u32 a3,
                                     u32 b0, u32 b1) {
    asm volatile(
        "mma.sync.aligned.m16n8k8.row.col.f32.tf32.tf32.f32 "
        "{%0,%1,%2,%3}, {%4,%5,%6,%7}, {%8,%9}, {%0,%1,%2,%3};"
        : "+f"(d[0]), "+f"(d[1]), "+f"(d[2]), "+f"(d[3])
        : "r"(a0), "r"(a1), "r"(a2), "r"(a3), "r"(b0), "r"(b1));
}
__device__ __forceinline__ u32 fbits(float v) { return __float_as_uint(v); }

// ---------------- scratch ----------------
__device__ float g_q[Bn*Rn*En];
__device__ float g_k[Bn*Cn*En];
__device__ float g_v[Bn*Cn*En];
__device__ float g_att[Bn*Rn*En];
__device__ float g_y[Bn*Rn*En];
__device__ float g_x[Bn*Rn*En];
__device__ float g_h[Bn*Rn*Fn];
__device__ float g_z[Bn*Rn*En];

// ---------------- tensor-core SGEMM 64x64, BK=16, 256 thr, tf32x3 ----------------
// D = A@B via mma.sync m16n8k8 tf32 with hi/lo split: hi*hi + hi*lo + lo*hi
// (error ~ |lo|^2 ~ 2^-22 — fp32-grade). 8 warps in 4(m)x2(n): each warp m16 x n32.
// Ah/Al: [m][k] pad 20 (conflict-free frag LDS). Bh/Bl: [n][k] pad 20.
template<bool RELU, bool RES>
__device__ __forceinline__
void gemm_tc_body(const float* __restrict__ A, const float* __restrict__ B,
                  const float* __restrict__ bias, const float* __restrict__ res,
                  float* __restrict__ C, int M, int N, int K)
{
    __shared__ float Ah[2][64][20];
    __shared__ float Al[2][64][20];
    __shared__ float Bh[2][64][20];
    __shared__ float Bl[2][64][20];

    const int tid = threadIdx.x;
    const int warp = tid >> 5;
    const int lane = tid & 31;
    const int wm = warp & 3;          // 0..3 -> m16 tile
    const int wn = warp >> 2;         // 0..1 -> n32 half
    const int m0 = blockIdx.y * 64;
    const int n0 = blockIdx.x * 64;

    const int arow = tid >> 2;            // 0..63
    const int acol = (tid & 3) * 4;       // 0,4,8,12
    const int brow = tid >> 4;            // 0..15 (k)
    const int bcol = (tid & 15) * 4;      // 0..60 (n)

    const float* Aptr = &A[(size_t)(m0 + arow) * K + acol];
    const float* Bptr = &B[(size_t)brow * N + n0 + bcol];

    float acc[4][4] = {};

    {   // prologue: tile 0 -> buffer 0
        float4 av = *reinterpret_cast<const float4*>(Aptr);
        float4 bv = *reinterpret_cast<const float4*>(Bptr);
        float h, l;
        split_tf32(av.x, h, l); Ah[0][arow][acol + 0] = h; Al[0][arow][acol + 0] = l;
        split_tf32(av.y, h, l); Ah[0][arow][acol + 1] = h; Al[0][arow][acol + 1] = l;
        split_tf32(av.z, h, l); Ah[0][arow][acol + 2] = h; Al[0][arow][acol + 2] = l;
        split_tf32(av.w, h, l); Ah[0][arow][acol + 3] = h; Al[0][arow][acol + 3] = l;
        split_tf32(bv.x, h, l); Bh[0][bcol + 0][brow] = h; Bl[0][bcol + 0][brow] = l;
        split_tf32(bv.y, h, l); Bh[0][bcol + 1][brow] = h; Bl[0][bcol + 1][brow] = l;
        split_tf32(bv.z, h, l); Bh[0][bcol + 2][brow] = h; Bl[0][bcol + 2][brow] = l;
        split_tf32(bv.w, h, l); Bh[0][bcol + 3][brow] = h; Bl[0][bcol + 3][brow] = l;
    }
    __syncthreads();

    const int r = lane >> 2;      // 0..7
    const int cc = lane & 3;      // 0..3

    int buf = 0;
    for (int k0 = 0; k0 < K; k0 += 16) {
        float4 nav, nbv;
        const bool more = (k0 + 16) < K;
        if (more) {
            nav = *reinterpret_cast<const float4*>(Aptr + (k0 + 16));
            nbv = *reinterpret_cast<const float4*>(Bptr + (size_t)(k0 + 16) * N);
        }
#pragma unroll
        for (int ks = 0; ks < 16; ks += 8) {
            u32 ah0 = fbits(Ah[buf][16 * wm + r][ks + cc]);
            u32 ah1 = fbits(Ah[buf][16 * wm + r + 8][ks + cc]);
            u32 ah2 = fbits(Ah[buf][16 * wm + r][ks + cc + 4]);
            u32 ah3 = fbits(Ah[buf][16 * wm + r + 8][ks + cc + 4]);
            u32 al0 = fbits(Al[buf][16 * wm + r][ks + cc]);
            u32 al1 = fbits(Al[buf][16 * wm + r + 8][ks + cc]);
            u32 al2 = fbits(Al[buf][16 * wm + r][ks + cc + 4]);
            u32 al3 = fbits(Al[buf][16 * wm + r + 8][ks + cc + 4]);
#pragma unroll
            for (int j = 0; j < 4; j++) {
                int nb = 32 * wn + 8 * j;
                u32 bh0 = fbits(Bh[buf][nb + r][ks + cc]);
                u32 bh1 = fbits(Bh[buf][nb + r][ks + cc + 4]);
                u32 bl0 = fbits(Bl[buf][nb + r][ks + cc]);
                u32 bl1 = fbits(Bl[buf][nb + r][ks + cc + 4]);
                mma8(acc[j], ah0, ah1, ah2, ah3, bh0, bh1);
                mma8(acc[j], ah0, ah1, ah2, ah3, bl0, bl1);
                mma8(acc[j], al0, al1, al2, al3, bh0, bh1);
            }
        }
        if (more) {
            __syncthreads();
            int nb2 = buf ^ 1;
            float h, l;
            split_tf32(nav.x, h, l); Ah[nb2][arow][acol + 0] = h; Al[nb2][arow][acol + 0] = l;
            split_tf32(nav.y, h, l); Ah[nb2][arow][acol + 1] = h; Al[nb2][arow][acol + 1] = l;
            split_tf32(nav.z, h, l); Ah[nb2][arow][acol + 2] = h; Al[nb2][arow][acol + 2] = l;
            split_tf32(nav.w, h, l); Ah[nb2][arow][acol + 3] = h; Al[nb2][arow][acol + 3] = l;
            split_tf32(nbv.x, h, l); Bh[nb2][bcol + 0][brow] = h; Bl[nb2][bcol + 0][brow] = l;
            split_tf32(nbv.y, h, l); Bh[nb2][bcol + 1][brow] = h; Bl[nb2][bcol + 1][brow] = l;
            split_tf32(nbv.z, h, l); Bh[nb2][bcol + 2][brow] = h; Bl[nb2][bcol + 2][brow] = l;
            split_tf32(nbv.w, h, l); Bh[nb2][bcol + 3][brow] = h; Bl[nb2][bcol + 3][brow] = l;
            __syncthreads();
            buf = nb2;
        }
    }

    // epilogue: c0:(r, 2c) c1:(r, 2c+1) c2:(r+8, 2c) c3:(r+8, 2c+1)
#pragma unroll
    for (int j = 0; j < 4; j++) {
        int ncol = n0 + 32 * wn + 8 * j + 2 * cc;
        int row0 = m0 + 16 * wm + r;
        int row1 = row0 + 8;
        float v00 = acc[j][0], v01 = acc[j][1];
        float v10 = acc[j][2], v11 = acc[j][3];
        if (bias) {
            float b0v = bias[ncol], b1v = bias[ncol + 1];
            v00 += b0v; v01 += b1v; v10 += b0v; v11 += b1v;
        }
        if (RES) {
            v00 += res[(size_t)row0 * N + ncol];
            v01 += res[(size_t)row0 * N + ncol + 1];
            v10 += res[(size_t)row1 * N + ncol];
            v11 += res[(size_t)row1 * N + ncol + 1];
        }
        if (RELU) {
            v00 = fmaxf(v00, 0.0f); v01 = fmaxf(v01, 0.0f);
            v10 = fmaxf(v10, 0.0f); v11 = fmaxf(v11, 0.0f);
        }
        float2 o0 = {v00, v01}, o1 = {v10, v11};
        *reinterpret_cast<float2*>(&C[(size_t)row0 * N + ncol]) = o0;
        *reinterpret_cast<float2*>(&C[(size_t)row1 * N + ncol]) = o1;
    }
}

template<bool RELU, bool RES>
__global__ __launch_bounds__(256, 3)
void gemm64(const float* __restrict__ A, const float* __restrict__ B,
            const float* __restrict__ bias, const float* __restrict__ res,
            float* __restrict__ C, int M, int N, int K)
{
    gemm_tc_body<RELU, RES>(A, B, bias, res, C, M, N, K);
}

__global__ __launch_bounds__(256, 3)
void qkv_gemm(const float* __restrict__ row_emb, const float* __restrict__ col_emb,
              const float* __restrict__ Wq, const float* __restrict__ Wk,
              const float* __restrict__ Wv,
              float* __restrict__ q, float* __restrict__ k, float* __restrict__ v)
{
    const float* A; const float* B; float* C;
    if (blockIdx.z == 0)      { A = row_emb; B = Wq; C = q; }
    else if (blockIdx.z == 1) { A = col_emb; B = Wk; C = k; }
    else                      { A = col_emb; B = Wv; C = v; }
    gemm_tc_body<false, false>(A, B, nullptr, nullptr, C, Bn * Rn, En, En);
}

// ---------------- fused attention (measured-best config, Q pre-scaled) ----------------
#define KV_STRIDE 20
#define ROWS_PER_BLK 32
#define ATTN_SMEM ((Cn * KV_STRIDE * 2 + ROWS_PER_BLK * Dn) * (int)sizeof(float))

__global__ __launch_bounds__(256, 2)
void attn_kernel(const float* __restrict__ Q, const float* __restrict__ K,
                 const float* __restrict__ V, const float* __restrict__ cost,
                 const float* __restrict__ mix1_w, const float* __restrict__ mix1_b,
                 const float* __restrict__ mix2_w, const float* __restrict__ mix2_b,
                 float* __restrict__ Out)
{
    extern __shared__ float sh[];
    float* ksh = sh;
    float* vsh = sh + Cn * KV_STRIDE;
    float* qsh = vsh + Cn * KV_STRIDE;

    __shared__ U2 swA[Mn];
    __shared__ U2 swB[Mn];
    __shared__ u64 sA2, sB2, sC2;

    const int tid = threadIdx.x;
    const int b = blockIdx.x >> 4;
    const int h = blockIdx.x & 15;
    const int r0 = blockIdx.y * ROWS_PER_BLK;

    if (tid < Mn) {
        float wd = mix1_w[h * 2 * Mn + tid];
        float wc = mix1_w[h * 2 * Mn + Mn + tid];
        float wb = mix1_b[h * Mn + tid];
        float w2h = 0.5f * mix2_w[h * Mn + tid];
        swA[tid].a = pk(wd, wd);
        swA[tid].b = pk(wc, wc);
        swB[tid].a = pk(wb, wb);
        swB[tid].b = pk(w2h, w2h);
    }
    if (tid == 0) {
        float Af = 0.0f, Bf = 0.0f, Cf = mix2_b[h];
#pragma unroll
        for (int m = 0; m < Mn; m++) {
            float w2h = 0.5f * mix2_w[h * Mn + m];
            Af = fmaf(w2h, mix1_w[h * 2 * Mn + m], Af);
            Bf = fmaf(w2h, mix1_w[h * 2 * Mn + Mn + m], Bf);
            Cf = fmaf(w2h, mix1_b[h * Mn + m], Cf);
        }
        sA2 = pk(Af, Af);
        sB2 = pk(Bf, Bf);
        sC2 = pk(Cf, Cf);
    }

    for (int idx = tid; idx < Cn * 4; idx += 256) {
        int c = idx >> 2, g = idx & 3;
        size_t src = ((size_t)(b * Cn + c)) * En + h * Dn + g * 4;
        *reinterpret_cast<float4*>(&ksh[c * KV_STRIDE + g * 4]) =
            *reinterpret_cast<const float4*>(&K[src]);
        *reinterpret_cast<float4*>(&vsh[c * KV_STRIDE + g * 4]) =
            *reinterpret_cast<const float4*>(&V[src]);
    }
    for (int idx = tid; idx < ROWS_PER_BLK * Dn; idx += 256) {
        int rr = idx >> 4, d = idx & 15;
        qsh[idx] = 0.25f * Q[((size_t)(b * Rn + r0 + rr)) * En + h * Dn + d];
    }
    __syncthreads();

    const int warp = tid >> 5;
    const int lane = tid & 31;
    const u64 A2 = sA2, B2 = sB2, C2 = sC2;

#pragma unroll 1
    for (int grp = 0; grp < 2; grp++) {
        const int ra = r0 + grp * 16 + warp;
        const int rb = ra + 8;
        const int qoff = grp * 16 + warp;

        const float* crA = &cost[((size_t)(b * Rn + ra)) * Cn];
        const float* crB = &cost[((size_t)(b * Rn + rb)) * Cn];

        u64 mx2[16];

#pragma unroll
        for (int st = 0; st < 2; st++) {
            u64 dot2[8], cv2[8];
            {
                const u64* pa = reinterpret_cast<const u64*>(&qsh[qoff * Dn]);
                const u64* pb = reinterpret_cast<const u64*>(&qsh[(qoff + 8) * Dn]);
                u64 qa[8], qb[8];
#pragma unroll
                for (int j = 0; j < 8; j++) { qa[j] = pa[j]; qb[j] = pb[j]; }
#pragma unroll
                for (int i = 0; i < 8; i++) {
                    int c = lane + 32 * (st * 8 + i);
                    const U2* kp = reinterpret_cast<const U2*>(&ksh[c * KV_STRIDE]);
                    U2 k01 = kp[0], k23 = kp[1], k45 = kp[2], k67 = kp[3];
                    u64 aA = 0, aB = 0;
                    aA = fma2(qa[0], k01.a, aA); aB = fma2(qb[0], k01.a, aB);
                    aA = fma2(qa[1], k01.b, aA); aB = fma2(qb[1], k01.b, aB);
                    aA = fma2(qa[2], k23.a, aA); aB = fma2(qb[2], k23.a, aB);
                    aA = fma2(qa[3], k23.b, aA); aB = fma2(qb[3], k23.b, aB);
                    aA = fma2(qa[4], k45.a, aA); aB = fma2(qb[4], k45.a, aB);
                    aA = fma2(qa[5], k45.b, aA); aB = fma2(qb[5], k45.b, aB);
                    aA = fma2(qa[6], k67.a, aA); aB = fma2(qb[6], k67.a, aB);
                    aA = fma2(qa[7], k67.b, aA); aB = fma2(qb[7], k67.b, aB);
                    float x0, x1, y0, y1;
                    upk(aA, x0, x1); upk(aB, y0, y1);
                    dot2[i] = pk(x0 + x1, y0 + y1);
                    cv2[i]  = pk(__ldg(&crA[c]), __ldg(&crB[c]));
                }
            }
            u64 acc[8] = {};
#pragma unroll
            for (int m = 0; m < Mn; m++) {
                U2 w1 = swA[m];
                U2 w2 = swB[m];
#pragma unroll
                for (int i = 0; i < 8; i++) {
                    u64 t = fma2(dot2[i], w1.a, fma2(cv2[i], w1.b, w2.a));
                    acc[i] = fma2(abs2(t), w2.b, acc[i]);
                }
            }
#pragma unroll
            for (int i = 0; i < 8; i++) {
                mx2[st * 8 + i] = fma2(dot2[i], A2, fma2(cv2[i], B2, add2(C2, acc[i])));
            }
        }

        float Ma = -1e30f, Mb = -1e30f;
#pragma unroll
        for (int i = 0; i < 16; i++) {
            float xa, xb; upk(mx2[i], xa, xb);
            Ma = fmaxf(Ma, xa); Mb = fmaxf(Mb, xb);
        }
#pragma unroll
        for (int off = 16; off; off >>= 1) {
            Ma = fmaxf(Ma, __shfl_xor_sync(0xFFFFFFFFu, Ma, off));
            Mb = fmaxf(Mb, __shfl_xor_sync(0xFFFFFFFFu, Mb, off));
        }

        u64 oa[8] = {}, ob[8] = {};
        float ssa = 0.0f, ssb = 0.0f;
#pragma unroll
        for (int i = 0; i < 16; i++) {
            int c = lane + 32 * i;
            float xa, xb; upk(mx2[i], xa, xb);
            float ea = __expf(xa - Ma);
            float eb = __expf(xb - Mb);
            ssa += ea; ssb += eb;
            const U2* vp = reinterpret_cast<const U2*>(&vsh[c * KV_STRIDE]);
            U2 v01 = vp[0], v23 = vp[1], v45 = vp[2], v67 = vp[3];
            u64 ea2 = pk(ea, ea), eb2 = pk(eb, eb);
            oa[0] = fma2(ea2, v01.a, oa[0]); ob[0] = fma2(eb2, v01.a, ob[0]);
            oa[1] = fma2(ea2, v01.b, oa[1]); ob[1] = fma2(eb2, v01.b, ob[1]);
            oa[2] = fma2(ea2, v23.a, oa[2]); ob[2] = fma2(eb2, v23.a, ob[2]);
            oa[3] = fma2(ea2, v23.b, oa[3]); ob[3] = fma2(eb2, v23.b, ob[3]);
            oa[4] = fma2(ea2, v45.a, oa[4]); ob[4] = fma2(eb2, v45.a, ob[4]);
            oa[5] = fma2(ea2, v45.b, oa[5]); ob[5] = fma2(eb2, v45.b, ob[5]);
            oa[6] = fma2(ea2, v67.a, oa[6]); ob[6] = fma2(eb2, v67.a, ob[6]);
            oa[7] = fma2(ea2, v67.b, oa[7]); ob[7] = fma2(eb2, v67.b, ob[7]);
        }

#pragma unroll
        for (int off = 16; off; off >>= 1) {
            ssa += __shfl_xor_sync(0xFFFFFFFFu, ssa, off);
            ssb += __shfl_xor_sync(0xFFFFFFFFu, ssb, off);
        }
        const float inva = 1.0f / ssa;
        const float invb = 1.0f / ssb;

        const bool hi16 = (lane & 16) != 0;
        u64 k8[8];
#pragma unroll
        for (int j = 0; j < 8; j++) {
            u64 kp_ = hi16 ? ob[j] : oa[j];
            u64 sd  = hi16 ? oa[j] : ob[j];
            k8[j] = add2(kp_, shflx2(sd, 16));
        }
        const bool hb8 = (lane & 8) != 0;
        u64 k4[4];
#pragma unroll
        for (int j = 0; j < 4; j++) {
            u64 kp_ = hb8 ? k8[j + 4] : k8[j];
            u64 sd  = hb8 ? k8[j] : k8[j + 4];
            k4[j] = add2(kp_, shflx2(sd, 8));
        }
        const bool hb4 = (lane & 4) != 0;
        u64 k2[2];
#pragma unroll
        for (int j = 0; j < 2; j++) {
            u64 kp_ = hb4 ? k4[j + 2] : k4[j];
            u64 sd  = hb4 ? k4[j] : k4[j + 2];
            k2[j] = add2(kp_, shflx2(sd, 4));
        }
        const bool hb2 = (lane & 2) != 0;
        u64 k1 = add2(hb2 ? k2[1] : k2[0], shflx2(hb2 ? k2[0] : k2[1], 2));
        float lo, hi; upk(k1, lo, hi);
        float kf = (lane & 1) ? hi : lo;
        float sf = (lane & 1) ? lo : hi;
        float val = kf + __shfl_xor_sync(0xFFFFFFFFu, sf, 1);

        const float invv = hi16 ? invb : inva;
        const int  rw   = hi16 ? rb : ra;
        Out[((size_t)(b * Rn + rw)) * En + h * Dn + (lane & 15)] = val * invv;
    }
}

// ---------------- instance norm (measured-best): grid (E/8, B), 256 thr ----------------
__global__ __launch_bounds__(256)
void inorm_kernel(const float* __restrict__ X, const float* __restrict__ gamma,
                  const float* __restrict__ beta, float* __restrict__ Y)
{
    const int b = blockIdx.y;
    const int tid = threadIdx.x;
    const int es = tid & 1;
    const int rg = tid >> 1;
    const int e4 = blockIdx.x * 2 + es;
    const int lane = tid & 31;
    const int warp = tid >> 5;
    const float4* xb = reinterpret_cast<const float4*>(X + (size_t)b * Rn * En);
    float4* yb = reinterpret_cast<float4*>(Y + (size_t)b * Rn * En);
    const int s4 = En / 4;

    float4 v[4];
#pragma unroll
    for (int j = 0; j < 4; j++)
        v[j] = xb[(size_t)(rg + 128 * j) * s4 + e4];

    float4 s = {0,0,0,0}, s2 = {0,0,0,0};
#pragma unroll
    for (int j = 0; j < 4; j++) {
        s.x += v[j].x; s.y += v[j].y; s.z += v[j].z; s.w += v[j].w;
        s2.x += v[j].x*v[j].x; s2.y += v[j].y*v[j].y;
        s2.z += v[j].z*v[j].z; s2.w += v[j].w*v[j].w;
    }
#pragma unroll
    for (int off = 16; off >= 2; off >>= 1) {
        s.x += __shfl_xor_sync(0xFFFFFFFFu, s.x, off);
        s.y += __shfl_xor_sync(0xFFFFFFFFu, s.y, off);
        s.z += __shfl_xor_sync(0xFFFFFFFFu, s.z, off);
        s.w += __shfl_xor_sync(0xFFFFFFFFu, s.w, off);
        s2.x += __shfl_xor_sync(0xFFFFFFFFu, s2.x, off);
        s2.y += __shfl_xor_sync(0xFFFFFFFFu, s2.y, off);
        s2.z += __shfl_xor_sync(0xFFFFFFFFu, s2.z, off);
        s2.w += __shfl_xor_sync(0xFFFFFFFFu, s2.w, off);
    }
    __shared__ float4 ws[8][2], ws2[8][2];
    __shared__ float4 sa4[2], sc4[2];
    if (lane < 2) { ws[warp][lane] = s; ws2[warp][lane] = s2; }
    __syncthreads();
    if (tid < 2) {
        float4 t = ws[0][tid], t2 = ws2[0][tid];
#pragma unroll
        for (int j = 1; j < 8; j++) {
            t.x += ws[j][tid].x; t.y += ws[j][tid].y; t.z += ws[j][tid].z; t.w += ws[j][tid].w;
            t2.x += ws2[j][tid].x; t2.y += ws2[j][tid].y; t2.z += ws2[j][tid].z; t2.w += ws2[j][tid].w;
        }
        float4 gm = reinterpret_cast<const float4*>(gamma)[blockIdx.x * 2 + tid];
        float4 bt = reinterpret_cast<const float4*>(beta)[blockIdx.x * 2 + tid];
        float4 a, c;
        float mean, var, rs;
        mean = t.x * (1.0f / Rn); var = t2.x * (1.0f / Rn) - mean * mean;
        rs = rsqrtf(var + 1e-5f); a.x = gm.x * rs; c.x = bt.x - mean * a.x;
        mean = t.y * (1.0f / Rn); var = t2.y * (1.0f / Rn) - mean * mean;
        rs = rsqrtf(var + 1e-5f); a.y = gm.y * rs; c.y = bt.y - mean * a.y;
        mean = t.z * (1.0f / Rn); var = t2.z * (1.0f / Rn) - mean * mean;
        rs = rsqrtf(var + 1e-5f); a.z = gm.z * rs; c.z = bt.z - mean * a.z;
        mean = t.w * (1.0f / Rn); var = t2.w * (1.0f / Rn) - mean * mean;
        rs = rsqrtf(var + 1e-5f); a.w = gm.w * rs; c.w = bt.w - mean * a.w;
        sa4[tid] = a; sc4[tid] = c;
    }
    __syncthreads();
    const float4 a = sa4[es], c = sc4[es];
#pragma unroll
    for (int j = 0; j < 4; j++) {
        float4 o;
        o.x = fmaf(v[j].x, a.x, c.x);
        o.y = fmaf(v[j].y, a.y, c.y);
        o.z = fmaf(v[j].z, a.z, c.z);
        o.w = fmaf(v[j].w, a.w, c.w);
        yb[(size_t)(rg + 128 * j) * s4 + e4] = o;
    }
}

// ---------------- launch ----------------
extern "C" void kernel_launch(void* const* d_in, const int* in_sizes, int n_in,
                              void* d_out, int out_size)
{
    const float* row_emb = (const float*)d_in[0];
    const float* col_emb = (const float*)d_in[1];
    const float* cost    = (const float*)d_in[2];
    const float* Wq      = (const float*)d_in[3];
    const float* Wk      = (const float*)d_in[4];
    const float* Wv      = (const float*)d_in[5];
    const float* mix1_w  = (const float*)d_in[6];
    const float* mix1_b  = (const float*)d_in[7];
    const float* mix2_w  = (const float*)d_in[8];
    const float* mix2_b  = (const float*)d_in[9];
    const float* Wc      = (const float*)d_in[10];
    const float* bc      = (const float*)d_in[11];
    const float* W1      = (const float*)d_in[12];
    const float* b1      = (const float*)d_in[13];
    const float* W2      = (const float*)d_in[14];
    const float* b2      = (const float*)d_in[15];
    const float* g1      = (const float*)d_in[16];
    const float* be1     = (const float*)d_in[17];
    const float* g2      = (const float*)d_in[18];
    const float* be2     = (const float*)d_in[19];
    float* out = (float*)d_out;

    float *q, *k, *v, *att, *y, *x, *hh, *z;
    cudaGetSymbolAddress((void**)&q,   g_q);
    cudaGetSymbolAddress((void**)&k,   g_k);
    cudaGetSymbolAddress((void**)&v,   g_v);
    cudaGetSymbolAddress((void**)&att, g_att);
    cudaGetSymbolAddress((void**)&y,   g_y);
    cudaGetSymbolAddress((void**)&x,   g_x);
    cudaGetSymbolAddress((void**)&hh,  g_h);
    cudaGetSymbolAddress((void**)&z,   g_z);

    cudaFuncSetAttribute(attn_kernel, cudaFuncAttributeMaxDynamicSharedMemorySize, ATTN_SMEM);

    const int MR = Bn * Rn;   // 2048

    {   // fused QKV (one launch, z selects)
        dim3 g(En / 64, MR / 64, 3);
        qkv_gemm<<<g, 256>>>(row_emb, col_emb, Wq, Wk, Wv, q, k, v);
    }
    {   // fused attention
        dim3 g(Bn * Hn, Rn / ROWS_PER_BLK);
        attn_kernel<<<g, 256, ATTN_SMEM>>>(q, k, v, cost, mix1_w, mix1_b, mix2_w, mix2_b, att);
    }
    {   // combine + residual
        dim3 g(En / 64, MR / 64);
        gemm64<false, true><<<g, 256>>>(att, Wc, bc, row_emb, y, MR, En, En);
    }
    {   // norm1
        dim3 g(En / 8, Bn);
        inorm_kernel<<<g, 256>>>(y, g1, be1, x);
    }
    {   // FFN
        dim3 ga(Fn / 64, MR / 64);
        gemm64<true, false><<<ga, 256>>>(x, W1, b1, nullptr, hh, MR, Fn, En);
        dim3 gb(En / 64, MR / 64);
        gemm64<false, true><<<gb, 256>>>(hh, W2, b2, x, z, MR, En, Fn);
    }
    {   // norm2 -> out
        dim3 g(En / 8, Bn);
        inorm_kernel<<<g, 256>>>(z, g2, be2, out);
    }
}

// round 16
// speedup vs baseline: 1.1797x; 1.1797x over previous
#include <cuda_runtime.h>
#include <math.h>

#define Bn 4
#define Rn 512
#define Cn 512
#define En 256
#define Hn 16
#define Dn 16
#define Mn 16
#define Fn 512

// ---------------- packed f32x2 helpers ----------------
typedef unsigned long long u64;
typedef unsigned int u32;
struct __align__(16) U2 { u64 a, b; };

__device__ __forceinline__ u64 pk(float lo, float hi) {
    u64 r; asm("mov.b64 %0,{%1,%2};" : "=l"(r) : "f"(lo), "f"(hi)); return r;
}
__device__ __forceinline__ void upk(u64 v, float& lo, float& hi) {
    asm("mov.b64 {%0,%1},%2;" : "=f"(lo), "=f"(hi) : "l"(v));
}
__device__ __forceinline__ u64 fma2(u64 a, u64 b, u64 c) {
    u64 d; asm("fma.rn.f32x2 %0,%1,%2,%3;" : "=l"(d) : "l"(a), "l"(b), "l"(c)); return d;
}
__device__ __forceinline__ u64 add2(u64 a, u64 b) {
    u64 d; asm("add.rn.f32x2 %0,%1,%2;" : "=l"(d) : "l"(a), "l"(b)); return d;
}
__device__ __forceinline__ u64 abs2(u64 x) { return x & 0x7FFFFFFF7FFFFFFFULL; }
__device__ __forceinline__ u64 shflx2(u64 v, int m) {
    float lo, hi; upk(v, lo, hi);
    lo = __shfl_xor_sync(0xFFFFFFFFu, lo, m);
    hi = __shfl_xor_sync(0xFFFFFFFFu, hi, m);
    return pk(lo, hi);
}

// ---------------- scratch ----------------
__device__ float g_q[Bn*Rn*En];
__device__ float g_k[Bn*Cn*En];
__device__ float g_v[Bn*Cn*En];
__device__ float g_att[Bn*Rn*En];
__device__ float g_y[Bn*Rn*En];
__device__ float g_x[Bn*Rn*En];
__device__ float g_h[Bn*Rn*Fn];
__device__ float g_z[Bn*Rn*En];

// ---------------- SGEMM 64x64, BK=16, 256 thr, double-buffered (measured-best) ----------------
// float4 epilogue: bias/res loads and C stores vectorized.
template<bool RELU, bool RES>
__device__ __forceinline__
void gemm_body(const float* __restrict__ A, const float* __restrict__ B,
               const float* __restrict__ bias, const float* __restrict__ res,
               float* __restrict__ C, int M, int N, int K)
{
    __shared__ float As[2][16][64];
    __shared__ float Bs[2][16][64];
    const int tid = threadIdx.x;
    const int tx = tid & 15;
    const int ty = tid >> 4;
    const int m0 = blockIdx.y * 64;
    const int n0 = blockIdx.x * 64;

    const int arow = tid >> 2;
    const int acol = (tid & 3) * 4;
    const int brow = tid >> 4;
    const int bcol = (tid & 15) * 4;

    const float* Aptr = &A[(size_t)(m0 + arow) * K + acol];
    const float* Bptr = &B[(size_t)brow * N + n0 + bcol];

    u64 acc2[4][2] = {};

    {
        float4 av = *reinterpret_cast<const float4*>(Aptr);
        float4 bv = *reinterpret_cast<const float4*>(Bptr);
        As[0][acol + 0][arow] = av.x;
        As[0][acol + 1][arow] = av.y;
        As[0][acol + 2][arow] = av.z;
        As[0][acol + 3][arow] = av.w;
        *reinterpret_cast<float4*>(&Bs[0][brow][bcol]) = bv;
    }
    __syncthreads();

    int buf = 0;
    for (int k0 = 0; k0 < K; k0 += 16) {
        float4 nav, nbv;
        const bool more = (k0 + 16) < K;
        if (more) {
            nav = *reinterpret_cast<const float4*>(Aptr + (k0 + 16));
            nbv = *reinterpret_cast<const float4*>(Bptr + (size_t)(k0 + 16) * N);
        }
#pragma unroll
        for (int k = 0; k < 16; k++) {
            float4 a4 = *reinterpret_cast<const float4*>(&As[buf][k][ty * 4]);
            float4 b4 = *reinterpret_cast<const float4*>(&Bs[buf][k][tx * 4]);
            u64 b01 = pk(b4.x, b4.y);
            u64 b23 = pk(b4.z, b4.w);
            u64 a0 = pk(a4.x, a4.x), a1 = pk(a4.y, a4.y);
            u64 a2 = pk(a4.z, a4.z), a3 = pk(a4.w, a4.w);
            acc2[0][0] = fma2(a0, b01, acc2[0][0]); acc2[0][1] = fma2(a0, b23, acc2[0][1]);
            acc2[1][0] = fma2(a1, b01, acc2[1][0]); acc2[1][1] = fma2(a1, b23, acc2[1][1]);
            acc2[2][0] = fma2(a2, b01, acc2[2][0]); acc2[2][1] = fma2(a2, b23, acc2[2][1]);
            acc2[3][0] = fma2(a3, b01, acc2[3][0]); acc2[3][1] = fma2(a3, b23, acc2[3][1]);
        }
        if (more) {
            __syncthreads();
            int nb = buf ^ 1;
            As[nb][acol + 0][arow] = nav.x;
            As[nb][acol + 1][arow] = nav.y;
            As[nb][acol + 2][arow] = nav.z;
            As[nb][acol + 3][arow] = nav.w;
            *reinterpret_cast<float4*>(&Bs[nb][brow][bcol]) = nbv;
            __syncthreads();
            buf = nb;
        }
    }

    // float4 epilogue
    const int ncol = n0 + tx * 4;
    float4 bi;
    if (bias) bi = *reinterpret_cast<const float4*>(&bias[ncol]);
#pragma unroll
    for (int i = 0; i < 4; i++) {
        int m = m0 + ty * 4 + i;
        float4 v;
        upk(acc2[i][0], v.x, v.y);
        upk(acc2[i][1], v.z, v.w);
        if (bias) { v.x += bi.x; v.y += bi.y; v.z += bi.z; v.w += bi.w; }
        if (RES) {
            float4 rv = *reinterpret_cast<const float4*>(&res[(size_t)m * N + ncol]);
            v.x += rv.x; v.y += rv.y; v.z += rv.z; v.w += rv.w;
        }
        if (RELU) {
            v.x = fmaxf(v.x, 0.0f); v.y = fmaxf(v.y, 0.0f);
            v.z = fmaxf(v.z, 0.0f); v.w = fmaxf(v.w, 0.0f);
        }
        *reinterpret_cast<float4*>(&C[(size_t)m * N + ncol]) = v;
    }
}

template<bool RELU, bool RES>
__global__ __launch_bounds__(256, 3)
void gemm64(const float* __restrict__ A, const float* __restrict__ B,
            const float* __restrict__ bias, const float* __restrict__ res,
            float* __restrict__ C, int M, int N, int K)
{
    gemm_body<RELU, RES>(A, B, bias, res, C, M, N, K);
}

__global__ __launch_bounds__(256, 3)
void qkv_gemm(const float* __restrict__ row_emb, const float* __restrict__ col_emb,
              const float* __restrict__ Wq, const float* __restrict__ Wk,
              const float* __restrict__ Wv,
              float* __restrict__ q, float* __restrict__ k, float* __restrict__ v)
{
    const float* A; const float* B; float* C;
    if (blockIdx.z == 0)      { A = row_emb; B = Wq; C = q; }
    else if (blockIdx.z == 1) { A = col_emb; B = Wk; C = k; }
    else                      { A = col_emb; B = Wv; C = v; }
    gemm_body<false, false>(A, B, nullptr, nullptr, C, Bn * Rn, En, En);
}

// ---------------- fused attention (measured-best config, Q pre-scaled) ----------------
#define KV_STRIDE 20
#define ROWS_PER_BLK 32
#define ATTN_SMEM ((Cn * KV_STRIDE * 2 + ROWS_PER_BLK * Dn) * (int)sizeof(float))

__global__ __launch_bounds__(256, 2)
void attn_kernel(const float* __restrict__ Q, const float* __restrict__ K,
                 const float* __restrict__ V, const float* __restrict__ cost,
                 const float* __restrict__ mix1_w, const float* __restrict__ mix1_b,
                 const float* __restrict__ mix2_w, const float* __restrict__ mix2_b,
                 float* __restrict__ Out)
{
    extern __shared__ float sh[];
    float* ksh = sh;
    float* vsh = sh + Cn * KV_STRIDE;
    float* qsh = vsh + Cn * KV_STRIDE;

    __shared__ U2 swA[Mn];
    __shared__ U2 swB[Mn];
    __shared__ u64 sA2, sB2, sC2;

    const int tid = threadIdx.x;
    const int b = blockIdx.x >> 4;
    const int h = blockIdx.x & 15;
    const int r0 = blockIdx.y * ROWS_PER_BLK;

    if (tid < Mn) {
        float wd = mix1_w[h * 2 * Mn + tid];
        float wc = mix1_w[h * 2 * Mn + Mn + tid];
        float wb = mix1_b[h * Mn + tid];
        float w2h = 0.5f * mix2_w[h * Mn + tid];
        swA[tid].a = pk(wd, wd);
        swA[tid].b = pk(wc, wc);
        swB[tid].a = pk(wb, wb);
        swB[tid].b = pk(w2h, w2h);
    }
    if (tid == 0) {
        float Af = 0.0f, Bf = 0.0f, Cf = mix2_b[h];
#pragma unroll
        for (int m = 0; m < Mn; m++) {
            float w2h = 0.5f * mix2_w[h * Mn + m];
            Af = fmaf(w2h, mix1_w[h * 2 * Mn + m], Af);
            Bf = fmaf(w2h, mix1_w[h * 2 * Mn + Mn + m], Bf);
            Cf = fmaf(w2h, mix1_b[h * Mn + m], Cf);
        }
        sA2 = pk(Af, Af);
        sB2 = pk(Bf, Bf);
        sC2 = pk(Cf, Cf);
    }

    for (int idx = tid; idx < Cn * 4; idx += 256) {
        int c = idx >> 2, g = idx & 3;
        size_t src = ((size_t)(b * Cn + c)) * En + h * Dn + g * 4;
        *reinterpret_cast<float4*>(&ksh[c * KV_STRIDE + g * 4]) =
            *reinterpret_cast<const float4*>(&K[src]);
        *reinterpret_cast<float4*>(&vsh[c * KV_STRIDE + g * 4]) =
            *reinterpret_cast<const float4*>(&V[src]);
    }
    for (int idx = tid; idx < ROWS_PER_BLK * Dn; idx += 256) {
        int rr = idx >> 4, d = idx & 15;
        qsh[idx] = 0.25f * Q[((size_t)(b * Rn + r0 + rr)) * En + h * Dn + d];
    }
    __syncthreads();

    const int warp = tid >> 5;
    const int lane = tid & 31;
    const u64 A2 = sA2, B2 = sB2, C2 = sC2;

#pragma unroll 1
    for (int grp = 0; grp < 2; grp++) {
        const int ra = r0 + grp * 16 + warp;
        const int rb = ra + 8;
        const int qoff = grp * 16 + warp;

        const float* crA = &cost[((size_t)(b * Rn + ra)) * Cn];
        const float* crB = &cost[((size_t)(b * Rn + rb)) * Cn];

        u64 mx2[16];

        // ---------------- phase 1: scores + mix MLP ----------------
#pragma unroll
        for (int st = 0; st < 2; st++) {
            u64 dot2[8], cv2[8];
            {
                const u64* pa = reinterpret_cast<const u64*>(&qsh[qoff * Dn]);
                const u64* pb = reinterpret_cast<const u64*>(&qsh[(qoff + 8) * Dn]);
                u64 qa[8], qb[8];
#pragma unroll
                for (int j = 0; j < 8; j++) { qa[j] = pa[j]; qb[j] = pb[j]; }
#pragma unroll
                for (int i = 0; i < 8; i++) {
                    int c = lane + 32 * (st * 8 + i);
                    const U2* kp = reinterpret_cast<const U2*>(&ksh[c * KV_STRIDE]);
                    U2 k01 = kp[0], k23 = kp[1], k45 = kp[2], k67 = kp[3];
                    u64 aA = 0, aB = 0;
                    aA = fma2(qa[0], k01.a, aA); aB = fma2(qb[0], k01.a, aB);
                    aA = fma2(qa[1], k01.b, aA); aB = fma2(qb[1], k01.b, aB);
                    aA = fma2(qa[2], k23.a, aA); aB = fma2(qb[2], k23.a, aB);
                    aA = fma2(qa[3], k23.b, aA); aB = fma2(qb[3], k23.b, aB);
                    aA = fma2(qa[4], k45.a, aA); aB = fma2(qb[4], k45.a, aB);
                    aA = fma2(qa[5], k45.b, aA); aB = fma2(qb[5], k45.b, aB);
                    aA = fma2(qa[6], k67.a, aA); aB = fma2(qb[6], k67.a, aB);
                    aA = fma2(qa[7], k67.b, aA); aB = fma2(qb[7], k67.b, aB);
                    float x0, x1, y0, y1;
                    upk(aA, x0, x1); upk(aB, y0, y1);
                    dot2[i] = pk(x0 + x1, y0 + y1);
                    cv2[i]  = pk(__ldg(&crA[c]), __ldg(&crB[c]));
                }
            }
            u64 acc[8] = {};
#pragma unroll
            for (int m = 0; m < Mn; m++) {
                U2 w1 = swA[m];
                U2 w2 = swB[m];
#pragma unroll
                for (int i = 0; i < 8; i++) {
                    u64 t = fma2(dot2[i], w1.a, fma2(cv2[i], w1.b, w2.a));
                    acc[i] = fma2(abs2(t), w2.b, acc[i]);
                }
            }
#pragma unroll
            for (int i = 0; i < 8; i++) {
                mx2[st * 8 + i] = fma2(dot2[i], A2, fma2(cv2[i], B2, add2(C2, acc[i])));
            }
        }

        // ---------------- phase 2: softmax + PV ----------------
        float Ma = -1e30f, Mb = -1e30f;
#pragma unroll
        for (int i = 0; i < 16; i++) {
            float xa, xb; upk(mx2[i], xa, xb);
            Ma = fmaxf(Ma, xa); Mb = fmaxf(Mb, xb);
        }
#pragma unroll
        for (int off = 16; off; off >>= 1) {
            Ma = fmaxf(Ma, __shfl_xor_sync(0xFFFFFFFFu, Ma, off));
            Mb = fmaxf(Mb, __shfl_xor_sync(0xFFFFFFFFu, Mb, off));
        }

        u64 oa[8] = {}, ob[8] = {};
        float ssa = 0.0f, ssb = 0.0f;
#pragma unroll
        for (int i = 0; i < 16; i++) {
            int c = lane + 32 * i;
            float xa, xb; upk(mx2[i], xa, xb);
            float ea = __expf(xa - Ma);
            float eb = __expf(xb - Mb);
            ssa += ea; ssb += eb;
            const U2* vp = reinterpret_cast<const U2*>(&vsh[c * KV_STRIDE]);
            U2 v01 = vp[0], v23 = vp[1], v45 = vp[2], v67 = vp[3];
            u64 ea2 = pk(ea, ea), eb2 = pk(eb, eb);
            oa[0] = fma2(ea2, v01.a, oa[0]); ob[0] = fma2(eb2, v01.a, ob[0]);
            oa[1] = fma2(ea2, v01.b, oa[1]); ob[1] = fma2(eb2, v01.b, ob[1]);
            oa[2] = fma2(ea2, v23.a, oa[2]); ob[2] = fma2(eb2, v23.a, ob[2]);
            oa[3] = fma2(ea2, v23.b, oa[3]); ob[3] = fma2(eb2, v23.b, ob[3]);
            oa[4] = fma2(ea2, v45.a, oa[4]); ob[4] = fma2(eb2, v45.a, ob[4]);
            oa[5] = fma2(ea2, v45.b, oa[5]); ob[5] = fma2(eb2, v45.b, ob[5]);
            oa[6] = fma2(ea2, v67.a, oa[6]); ob[6] = fma2(eb2, v67.a, ob[6]);
            oa[7] = fma2(ea2, v67.b, oa[7]); ob[7] = fma2(eb2, v67.b, ob[7]);
        }

#pragma unroll
        for (int off = 16; off; off >>= 1) {
            ssa += __shfl_xor_sync(0xFFFFFFFFu, ssa, off);
            ssb += __shfl_xor_sync(0xFFFFFFFFu, ssb, off);
        }
        const float inva = 1.0f / ssa;
        const float invb = 1.0f / ssb;

        // ---- recursive-halving reduction: lane -> (row = lane>=16, d = lane&15) ----
        const bool hi16 = (lane & 16) != 0;
        u64 k8[8];
#pragma unroll
        for (int j = 0; j < 8; j++) {
            u64 kp_ = hi16 ? ob[j] : oa[j];
            u64 sd  = hi16 ? oa[j] : ob[j];
            k8[j] = add2(kp_, shflx2(sd, 16));
        }
        const bool hb8 = (lane & 8) != 0;
        u64 k4[4];
#pragma unroll
        for (int j = 0; j < 4; j++) {
            u64 kp_ = hb8 ? k8[j + 4] : k8[j];
            u64 sd  = hb8 ? k8[j] : k8[j + 4];
            k4[j] = add2(kp_, shflx2(sd, 8));
        }
        const bool hb4 = (lane & 4) != 0;
        u64 k2[2];
#pragma unroll
        for (int j = 0; j < 2; j++) {
            u64 kp_ = hb4 ? k4[j + 2] : k4[j];
            u64 sd  = hb4 ? k4[j] : k4[j + 2];
            k2[j] = add2(kp_, shflx2(sd, 4));
        }
        const bool hb2 = (lane & 2) != 0;
        u64 k1 = add2(hb2 ? k2[1] : k2[0], shflx2(hb2 ? k2[0] : k2[1], 2));
        float lo, hi; upk(k1, lo, hi);
        float kf = (lane & 1) ? hi : lo;
        float sf = (lane & 1) ? lo : hi;
        float val = kf + __shfl_xor_sync(0xFFFFFFFFu, sf, 1);

        const float invv = hi16 ? invb : inva;
        const int  rw   = hi16 ? rb : ra;
        Out[((size_t)(b * Rn + rw)) * En + h * Dn + (lane & 15)] = val * invv;
    }
}

// ---------------- instance norm (measured-best): grid (E/8, B), 256 thr ----------------
__global__ __launch_bounds__(256)
void inorm_kernel(const float* __restrict__ X, const float* __restrict__ gamma,
                  const float* __restrict__ beta, float* __restrict__ Y)
{
    const int b = blockIdx.y;
    const int tid = threadIdx.x;
    const int es = tid & 1;
    const int rg = tid >> 1;
    const int e4 = blockIdx.x * 2 + es;
    const int lane = tid & 31;
    const int warp = tid >> 5;
    const float4* xb = reinterpret_cast<const float4*>(X + (size_t)b * Rn * En);
    float4* yb = reinterpret_cast<float4*>(Y + (size_t)b * Rn * En);
    const int s4 = En / 4;

    float4 v[4];
#pragma unroll
    for (int j = 0; j < 4; j++)
        v[j] = xb[(size_t)(rg + 128 * j) * s4 + e4];

    float4 s = {0,0,0,0}, s2 = {0,0,0,0};
#pragma unroll
    for (int j = 0; j < 4; j++) {
        s.x += v[j].x; s.y += v[j].y; s.z += v[j].z; s.w += v[j].w;
        s2.x += v[j].x*v[j].x; s2.y += v[j].y*v[j].y;
        s2.z += v[j].z*v[j].z; s2.w += v[j].w*v[j].w;
    }
#pragma unroll
    for (int off = 16; off >= 2; off >>= 1) {
        s.x += __shfl_xor_sync(0xFFFFFFFFu, s.x, off);
        s.y += __shfl_xor_sync(0xFFFFFFFFu, s.y, off);
        s.z += __shfl_xor_sync(0xFFFFFFFFu, s.z, off);
        s.w += __shfl_xor_sync(0xFFFFFFFFu, s.w, off);
        s2.x += __shfl_xor_sync(0xFFFFFFFFu, s2.x, off);
        s2.y += __shfl_xor_sync(0xFFFFFFFFu, s2.y, off);
        s2.z += __shfl_xor_sync(0xFFFFFFFFu, s2.z, off);
        s2.w += __shfl_xor_sync(0xFFFFFFFFu, s2.w, off);
    }
    __shared__ float4 ws[8][2], ws2[8][2];
    __shared__ float4 sa4[2], sc4[2];
    if (lane < 2) { ws[warp][lane] = s; ws2[warp][lane] = s2; }
    __syncthreads();
    if (tid < 2) {
        float4 t = ws[0][tid], t2 = ws2[0][tid];
#pragma unroll
        for (int j = 1; j < 8; j++) {
            t.x += ws[j][tid].x; t.y += ws[j][tid].y; t.z += ws[j][tid].z; t.w += ws[j][tid].w;
            t2.x += ws2[j][tid].x; t2.y += ws2[j][tid].y; t2.z += ws2[j][tid].z; t2.w += ws2[j][tid].w;
        }
        float4 gm = reinterpret_cast<const float4*>(gamma)[blockIdx.x * 2 + tid];
        float4 bt = reinterpret_cast<const float4*>(beta)[blockIdx.x * 2 + tid];
        float4 a, c;
        float mean, var, rs;
        mean = t.x * (1.0f / Rn); var = t2.x * (1.0f / Rn) - mean * mean;
        rs = rsqrtf(var + 1e-5f); a.x = gm.x * rs; c.x = bt.x - mean * a.x;
        mean = t.y * (1.0f / Rn); var = t2.y * (1.0f / Rn) - mean * mean;
        rs = rsqrtf(var + 1e-5f); a.y = gm.y * rs; c.y = bt.y - mean * a.y;
        mean = t.z * (1.0f / Rn); var = t2.z * (1.0f / Rn) - mean * mean;
        rs = rsqrtf(var + 1e-5f); a.z = gm.z * rs; c.z = bt.z - mean * a.z;
        mean = t.w * (1.0f / Rn); var = t2.w * (1.0f / Rn) - mean * mean;
        rs = rsqrtf(var + 1e-5f); a.w = gm.w * rs; c.w = bt.w - mean * a.w;
        sa4[tid] = a; sc4[tid] = c;
    }
    __syncthreads();
    const float4 a = sa4[es], c = sc4[es];
#pragma unroll
    for (int j = 0; j < 4; j++) {
        float4 o;
        o.x = fmaf(v[j].x, a.x, c.x);
        o.y = fmaf(v[j].y, a.y, c.y);
        o.z = fmaf(v[j].z, a.z, c.z);
        o.w = fmaf(v[j].w, a.w, c.w);
        yb[(size_t)(rg + 128 * j) * s4 + e4] = o;
    }
}

// ---------------- launch ----------------
extern "C" void kernel_launch(void* const* d_in, const int* in_sizes, int n_in,
                              void* d_out, int out_size)
{
    const float* row_emb = (const float*)d_in[0];
    const float* col_emb = (const float*)d_in[1];
    const float* cost    = (const float*)d_in[2];
    const float* Wq      = (const float*)d_in[3];
    const float* Wk      = (const float*)d_in[4];
    const float* Wv      = (const float*)d_in[5];
    const float* mix1_w  = (const float*)d_in[6];
    const float* mix1_b  = (const float*)d_in[7];
    const float* mix2_w  = (const float*)d_in[8];
    const float* mix2_b  = (const float*)d_in[9];
    const float* Wc      = (const float*)d_in[10];
    const float* bc      = (const float*)d_in[11];
    const float* W1      = (const float*)d_in[12];
    const float* b1      = (const float*)d_in[13];
    const float* W2      = (const float*)d_in[14];
    const float* b2      = (const float*)d_in[15];
    const float* g1      = (const float*)d_in[16];
    const float* be1     = (const float*)d_in[17];
    const float* g2      = (const float*)d_in[18];
    const float* be2     = (const float*)d_in[19];
    float* out = (float*)d_out;

    float *q, *k, *v, *att, *y, *x, *hh, *z;
    cudaGetSymbolAddress((void**)&q,   g_q);
    cudaGetSymbolAddress((void**)&k,   g_k);
    cudaGetSymbolAddress((void**)&v,   g_v);
    cudaGetSymbolAddress((void**)&att, g_att);
    cudaGetSymbolAddress((void**)&y,   g_y);
    cudaGetSymbolAddress((void**)&x,   g_x);
    cudaGetSymbolAddress((void**)&hh,  g_h);
    cudaGetSymbolAddress((void**)&z,   g_z);

    cudaFuncSetAttribute(attn_kernel, cudaFuncAttributeMaxDynamicSharedMemorySize, ATTN_SMEM);

    const int MR = Bn * Rn;   // 2048

    {   // fused QKV (one launch, z selects)
        dim3 g(En / 64, MR / 64, 3);
        qkv_gemm<<<g, 256>>>(row_emb, col_emb, Wq, Wk, Wv, q, k, v);
    }
    {   // fused attention
        dim3 g(Bn * Hn, Rn / ROWS_PER_BLK);
        attn_kernel<<<g, 256, ATTN_SMEM>>>(q, k, v, cost, mix1_w, mix1_b, mix2_w, mix2_b, att);
    }
    {   // combine + residual
        dim3 g(En / 64, MR / 64);
        gemm64<false, true><<<g, 256>>>(att, Wc, bc, row_emb, y, MR, En, En);
    }
    {   // norm1
        dim3 g(En / 8, Bn);
        inorm_kernel<<<g, 256>>>(y, g1, be1, x);
    }
    {   // FFN
        dim3 ga(Fn / 64, MR / 64);
        gemm64<true, false><<<ga, 256>>>(x, W1, b1, nullptr, hh, MR, Fn, En);
        dim3 gb(En / 64, MR / 64);
        gemm64<false, true><<<gb, 256>>>(hh, W2, b2, x, z, MR, En, Fn);
    }
    {   // norm2 -> out
        dim3 g(En / 8, Bn);
        inorm_kernel<<<g, 256>>>(z, g2, be2, out);
    }
}